// round 15
// baseline (speedup 1.0000x reference)
#include <cuda_runtime.h>

// Problem constants (fixed shapes from reference)
#define B_    4
#define C_    256
#define HW    65536      // 256*256 pixels per (b, c)
#define K_    19
#define COUNT_THRESH 6
#define EPS_  1e-5f

// Tiling
#define CBLK  128        // channels per block
#define TPX   128        // pixels per tile
#define TILES 8          // tiles per block
#define SEGPX (TPX*TILES)    // 1024 pixels per block
#define SEGS  (HW/SEGPX)     // 64 pixel segments
#define PAD   129            // padded tile row (floats) -> conflict-free transpose

// Dynamic smem layout (floats):
//   tile  : TPX*PAD                  (66048 B)
//   acc   : K_*CBLK float2           (19456 B)
//   lists : TILES*TPX u16            ( 2048 B)
//   offs  : TILES*(K_+1) int         (  640 B)
//   cnt   : K_ int                   (   76 B)
#define SMEM_TILE_F  (TPX*PAD)
#define SMEM_ACC_F   (K_*CBLK*2)
#define SMEM_BYTES   ((SMEM_TILE_F + SMEM_ACC_F)*4 + TILES*TPX*2 + TILES*(K_+1)*4 + K_*4)

// Scratch (device globals; zeroed every launch so graph replay is safe)
__device__ float d_scrS[B_*K_*C_];
__device__ float d_scrQ[B_*K_*C_];
__device__ int   d_cnt [B_*K_];

__global__ void zero_kernel() {
    int i = blockIdx.x * blockDim.x + threadIdx.x;
    if (i < B_*K_*C_) { d_scrS[i] = 0.f; d_scrQ[i] = 0.f; }
    if (i < B_*K_)    d_cnt[i] = 0;
}

// Per-batch label histogram -> d_cnt[b*K_+k]
__global__ void hist_kernel(const int* __restrict__ y) {
    __shared__ int h[K_];
    if (threadIdx.x < K_) h[threadIdx.x] = 0;
    __syncthreads();
    const int b     = blockIdx.y;
    const int chunk = HW / 16;                 // 16 chunks per batch
    const int* yp   = y + (size_t)b * HW + blockIdx.x * chunk;
    for (int n = threadIdx.x; n < chunk; n += blockDim.x)
        atomicAdd(&h[yp[n]], 1);
    __syncthreads();
    if (threadIdx.x < K_)
        atomicAdd(&d_cnt[b*K_ + threadIdx.x], h[threadIdx.x]);
}

// Main: block = (pixel segment, channel group, batch). thread = channel.
// Per 128-pixel tile: counting-sort pixels by label, stage x tile through
// padded smem (transpose), then per class-run accumulate sum/sumsq in regs.
__global__ void __launch_bounds__(CBLK)
moment_main_kernel(const float* __restrict__ x, const int* __restrict__ y) {
    extern __shared__ float smem[];
    float*          tile  = smem;
    float2*         acc   = (float2*)(smem + SMEM_TILE_F);
    unsigned short* lists = (unsigned short*)(smem + SMEM_TILE_F + SMEM_ACC_F);
    int*            offs  = (int*)(lists + TILES*TPX);
    int*            cnt   = offs + TILES*(K_+1);

    const int tid = threadIdx.x;                // channel within group / pixel within tile
    const int b   = blockIdx.z;
    const int c0  = blockIdx.y * CBLK;
    const int n0  = blockIdx.x * SEGPX;

    // zero per-block accumulators (exclusive per-thread slots)
    #pragma unroll
    for (int k = 0; k < K_; ++k)
        acc[k*CBLK + tid] = make_float2(0.f, 0.f);

    // ---- label phase: counting sort per tile ----
    int lab[TILES];
    const int* yp = y + (size_t)b * HW + n0;
    #pragma unroll
    for (int t = 0; t < TILES; ++t)
        lab[t] = yp[t*TPX + tid];

    for (int t = 0; t < TILES; ++t) {
        if (tid < K_) cnt[tid] = 0;
        __syncthreads();
        atomicAdd(&cnt[lab[t]], 1);
        __syncthreads();
        if (tid == 0) {
            int run = 0;
            #pragma unroll
            for (int k = 0; k < K_; ++k) {
                int c = cnt[k];
                offs[t*(K_+1) + k] = run;
                cnt[k] = run;           // reuse as scatter cursor
                run += c;
            }
            offs[t*(K_+1) + K_] = run;  // == TPX
        }
        __syncthreads();
        int pos = atomicAdd(&cnt[lab[t]], 1);
        lists[t*TPX + pos] = (unsigned short)(tid * PAD);   // pre-multiplied row offset
        __syncthreads();
    }

    // ---- main phase: stage + accumulate ----
    const float* xp = x + ((size_t)(b*C_ + c0)) * HW + n0;
    for (int t = 0; t < TILES; ++t) {
        // stage: thread = pixel (coalesced global), padded smem row (conflict-free)
        const float* xt = xp + t*TPX + tid;
        #pragma unroll 8
        for (int ch = 0; ch < CBLK; ++ch)
            tile[tid*PAD + ch] = xt[(size_t)ch * HW];
        __syncthreads();

        // compute: thread = channel; label uniform per step; regs accumulate per run
        const unsigned short* lst = lists + t*TPX;
        const int*            of  = offs  + t*(K_+1);
        for (int k = 0; k < K_; ++k) {
            float s = 0.f, q = 0.f;
            const int e = of[k+1];
            for (int j = of[k]; j < e; ++j) {
                float v = tile[(int)lst[j] + tid];
                s += v;
                q = fmaf(v, v, q);
            }
            float2 a = acc[k*CBLK + tid];
            a.x += s; a.y += q;
            acc[k*CBLK + tid] = a;
        }
        __syncthreads();
    }

    // ---- flush: one atomic pair per (class, channel) per block ----
    const int base = (b*K_)*C_ + c0 + tid;
    #pragma unroll
    for (int k = 0; k < K_; ++k) {
        float2 a = acc[k*CBLK + tid];
        atomicAdd(&d_scrS[base + k*C_], a.x);
        atomicAdd(&d_scrQ[base + k*C_], a.y);
    }
}

// Finalize: means [B,K,C] | stds [B,K,C] | valid [B,K]  (all float32)
__global__ void finalize_kernel(float* __restrict__ out) {
    const int bk = blockIdx.x;      // 0..B*K-1
    const int c  = threadIdx.x;     // 0..C-1
    const int cc = d_cnt[bk];
    const float n     = (float)cc;
    const bool  valid = cc > COUNT_THRESH;
    const float s = d_scrS[bk*C_ + c];
    const float q = d_scrQ[bk*C_ + c];
    const float mean = s / fmaxf(n, 1.f);
    float var = (q - n*mean*mean) / fmaxf(n - 1.f, 1.f);
    var = fmaxf(var, 0.f);
    const float sd = sqrtf(valid ? var : 1.f) + EPS_;
    out[bk*C_ + c]            = valid ? mean : 0.f;
    out[B_*K_*C_ + bk*C_ + c] = valid ? sd   : 0.f;
    if (c == 0)
        out[2*B_*K_*C_ + bk] = valid ? 1.f : 0.f;
}

extern "C" void kernel_launch(void* const* d_in, const int* in_sizes, int n_in,
                              void* d_out, int out_size) {
    const float* x = (const float*)d_in[0];   // [B, C, H, W] f32
    const int*   y = (const int*)d_in[1];     // [B, H, W] int32
    float* out = (float*)d_out;

    zero_kernel<<<(B_*K_*C_ + 255)/256, 256>>>();

    dim3 hgrid(16, B_);
    hist_kernel<<<hgrid, 256>>>(y);

    cudaFuncSetAttribute(moment_main_kernel,
                         cudaFuncAttributeMaxDynamicSharedMemorySize, SMEM_BYTES);
    dim3 grid(SEGS, C_/CBLK, B_);   // 64 x 2 x 4 = 512 blocks
    moment_main_kernel<<<grid, CBLK, SMEM_BYTES>>>(x, y);

    finalize_kernel<<<B_*K_, C_>>>(out);
}

// round 16
// speedup vs baseline: 1.0025x; 1.0025x over previous
#include <cuda_runtime.h>

// Problem constants (fixed shapes from reference)
#define B_    4
#define C_    256
#define HW    65536      // 256*256 pixels per (b, c)
#define K_    19
#define COUNT_THRESH 6
#define EPS_  1e-5f

// Tiling
#define CBLK  128        // channels per block
#define TPX   128        // pixels per tile
#define TILES 8          // tiles per block
#define SEGPX (TPX*TILES)    // 1024 pixels per block
#define SEGS  (HW/SEGPX)     // 64 pixel segments
#define PAD   129            // padded tile row (floats) -> conflict-free transpose

// Dynamic smem layout (floats):
//   tile  : TPX*PAD                  (66048 B)
//   acc   : K_*CBLK float2           (19456 B)
//   lists : TILES*TPX u16            ( 2048 B)
//   offs  : TILES*(K_+1) int         (  640 B)
//   cnt   : K_ int                   (   76 B)
#define SMEM_TILE_F  (TPX*PAD)
#define SMEM_ACC_F   (K_*CBLK*2)
#define SMEM_BYTES   ((SMEM_TILE_F + SMEM_ACC_F)*4 + TILES*TPX*2 + TILES*(K_+1)*4 + K_*4)

// Scratch (device globals; zeroed every launch so graph replay is safe)
__device__ float d_scrS[B_*K_*C_];
__device__ float d_scrQ[B_*K_*C_];
__device__ int   d_cnt [B_*K_];

__global__ void zero_kernel() {
    int i = blockIdx.x * blockDim.x + threadIdx.x;
    if (i < B_*K_*C_) { d_scrS[i] = 0.f; d_scrQ[i] = 0.f; }
    if (i < B_*K_)    d_cnt[i] = 0;
}

// Per-batch label histogram -> d_cnt[b*K_+k]
__global__ void hist_kernel(const int* __restrict__ y) {
    __shared__ int h[K_];
    if (threadIdx.x < K_) h[threadIdx.x] = 0;
    __syncthreads();
    const int b     = blockIdx.y;
    const int chunk = HW / 16;                 // 16 chunks per batch
    const int* yp   = y + (size_t)b * HW + blockIdx.x * chunk;
    for (int n = threadIdx.x; n < chunk; n += blockDim.x)
        atomicAdd(&h[yp[n]], 1);
    __syncthreads();
    if (threadIdx.x < K_)
        atomicAdd(&d_cnt[b*K_ + threadIdx.x], h[threadIdx.x]);
}

// Main: block = (pixel segment, channel group, batch). thread = channel.
// Per 128-pixel tile: counting-sort pixels by label, stage x tile through
// padded smem (transpose), then per class-run accumulate sum/sumsq in regs.
__global__ void __launch_bounds__(CBLK)
moment_main_kernel(const float* __restrict__ x, const int* __restrict__ y) {
    extern __shared__ float smem[];
    float*          tile  = smem;
    float2*         acc   = (float2*)(smem + SMEM_TILE_F);
    unsigned short* lists = (unsigned short*)(smem + SMEM_TILE_F + SMEM_ACC_F);
    int*            offs  = (int*)(lists + TILES*TPX);
    int*            cnt   = offs + TILES*(K_+1);

    const int tid = threadIdx.x;                // channel within group / pixel within tile
    const int b   = blockIdx.z;
    const int c0  = blockIdx.y * CBLK;
    const int n0  = blockIdx.x * SEGPX;

    // zero per-block accumulators (exclusive per-thread slots)
    #pragma unroll
    for (int k = 0; k < K_; ++k)
        acc[k*CBLK + tid] = make_float2(0.f, 0.f);

    // ---- label phase: counting sort per tile ----
    int lab[TILES];
    const int* yp = y + (size_t)b * HW + n0;
    #pragma unroll
    for (int t = 0; t < TILES; ++t)
        lab[t] = yp[t*TPX + tid];

    for (int t = 0; t < TILES; ++t) {
        if (tid < K_) cnt[tid] = 0;
        __syncthreads();
        atomicAdd(&cnt[lab[t]], 1);
        __syncthreads();
        if (tid == 0) {
            int run = 0;
            #pragma unroll
            for (int k = 0; k < K_; ++k) {
                int c = cnt[k];
                offs[t*(K_+1) + k] = run;
                cnt[k] = run;           // reuse as scatter cursor
                run += c;
            }
            offs[t*(K_+1) + K_] = run;  // == TPX
        }
        __syncthreads();
        int pos = atomicAdd(&cnt[lab[t]], 1);
        lists[t*TPX + pos] = (unsigned short)(tid * PAD);   // pre-multiplied row offset
        __syncthreads();
    }

    // ---- main phase: stage + accumulate ----
    const float* xp = x + ((size_t)(b*C_ + c0)) * HW + n0;
    for (int t = 0; t < TILES; ++t) {
        // stage: thread = pixel (coalesced global), padded smem row (conflict-free)
        const float* xt = xp + t*TPX + tid;
        #pragma unroll 8
        for (int ch = 0; ch < CBLK; ++ch)
            tile[tid*PAD + ch] = xt[(size_t)ch * HW];
        __syncthreads();

        // compute: thread = channel; label uniform per step; regs accumulate per run
        const unsigned short* lst = lists + t*TPX;
        const int*            of  = offs  + t*(K_+1);
        for (int k = 0; k < K_; ++k) {
            float s = 0.f, q = 0.f;
            const int e = of[k+1];
            for (int j = of[k]; j < e; ++j) {
                float v = tile[(int)lst[j] + tid];
                s += v;
                q = fmaf(v, v, q);
            }
            float2 a = acc[k*CBLK + tid];
            a.x += s; a.y += q;
            acc[k*CBLK + tid] = a;
        }
        __syncthreads();
    }

    // ---- flush: one atomic pair per (class, channel) per block ----
    const int base = (b*K_)*C_ + c0 + tid;
    #pragma unroll
    for (int k = 0; k < K_; ++k) {
        float2 a = acc[k*CBLK + tid];
        atomicAdd(&d_scrS[base + k*C_], a.x);
        atomicAdd(&d_scrQ[base + k*C_], a.y);
    }
}

// Finalize: means [B,K,C] | stds [B,K,C] | valid [B,K]  (all float32)
__global__ void finalize_kernel(float* __restrict__ out) {
    const int bk = blockIdx.x;      // 0..B*K-1
    const int c  = threadIdx.x;     // 0..C-1
    const int cc = d_cnt[bk];
    const float n     = (float)cc;
    const bool  valid = cc > COUNT_THRESH;
    const float s = d_scrS[bk*C_ + c];
    const float q = d_scrQ[bk*C_ + c];
    const float mean = s / fmaxf(n, 1.f);
    float var = (q - n*mean*mean) / fmaxf(n - 1.f, 1.f);
    var = fmaxf(var, 0.f);
    const float sd = sqrtf(valid ? var : 1.f) + EPS_;
    out[bk*C_ + c]            = valid ? mean : 0.f;
    out[B_*K_*C_ + bk*C_ + c] = valid ? sd   : 0.f;
    if (c == 0)
        out[2*B_*K_*C_ + bk] = valid ? 1.f : 0.f;
}

extern "C" void kernel_launch(void* const* d_in, const int* in_sizes, int n_in,
                              void* d_out, int out_size) {
    const float* x = (const float*)d_in[0];   // [B, C, H, W] f32
    const int*   y = (const int*)d_in[1];     // [B, H, W] int32
    float* out = (float*)d_out;

    zero_kernel<<<(B_*K_*C_ + 255)/256, 256>>>();

    dim3 hgrid(16, B_);
    hist_kernel<<<hgrid, 256>>>(y);

    cudaFuncSetAttribute(moment_main_kernel,
                         cudaFuncAttributeMaxDynamicSharedMemorySize, SMEM_BYTES);
    dim3 grid(SEGS, C_/CBLK, B_);   // 64 x 2 x 4 = 512 blocks
    moment_main_kernel<<<grid, CBLK, SMEM_BYTES>>>(x, y);

    finalize_kernel<<<B_*K_, C_>>>(out);
}

// round 17
// speedup vs baseline: 1.5640x; 1.5601x over previous
#include <cuda_runtime.h>

// Problem constants (fixed shapes from reference)
#define B_    4
#define C_    256
#define HW    65536      // 256*256 pixels per (b, c)
#define K_    19
#define COUNT_THRESH 6
#define EPS_  1e-5f

// Tiling
#define CBLK   128       // channels per block (= threads)
#define TPX    64        // pixels per tile
#define TILES  8         // tiles per block
#define SEGPX  (TPX*TILES)   // 512 pixels per block
#define SEGS   (HW/SEGPX)    // 128 pixel segments
#define ROWLEN 65            // tile row length in floats ([ch][px], 64 + 1 pad)
                             // lane stride 65 == 1 mod 32 -> conflict-free compute LDS

// Dynamic smem layout:
//   tile  : CBLK*ROWLEN floats   (33280 B)
//   lists : TILES*TPX u16        ( 1024 B)
//   offs  : TILES*(K_+1) int     (  640 B)
//   cnt   : 2*K_ int             (  152 B)
#define SMEM_TILE_F (CBLK*ROWLEN)
#define SMEM_BYTES  (SMEM_TILE_F*4 + TILES*TPX*2 + TILES*(K_+1)*4 + 2*K_*4)

// Scratch (device globals; zeroed every launch so graph replay is safe)
__device__ float d_scrS[B_*K_*C_];
__device__ float d_scrQ[B_*K_*C_];
__device__ int   d_cnt [B_*K_];

__global__ void zero_kernel() {
    int i = blockIdx.x * blockDim.x + threadIdx.x;
    if (i < B_*K_*C_) { d_scrS[i] = 0.f; d_scrQ[i] = 0.f; }
    if (i < B_*K_)    d_cnt[i] = 0;
}

// Main: block = (pixel segment, channel group, batch).
// Per 64-pixel tile: counting-sort pixels by label (2 tiles per round),
// stage x tile via LDG.128 into [ch][px] smem, then per class-run
// accumulate sum/sumsq in REGISTERS (k-loop fully unrolled, K=19).
__global__ void __launch_bounds__(CBLK)
moment_main_kernel(const float* __restrict__ x, const int* __restrict__ y) {
    extern __shared__ float smem[];
    float*          tile  = smem;
    unsigned short* lists = (unsigned short*)(smem + SMEM_TILE_F);
    int*            offs  = (int*)(lists + TILES*TPX);
    int*            cnt   = offs + TILES*(K_+1);

    const int tid = threadIdx.x;
    const int b   = blockIdx.z;
    const int c0  = blockIdx.y * CBLK;
    const int n0  = blockIdx.x * SEGPX;

    // ---- label phase: counting sort, 2 tiles per round ----
    {
        const int p = tid & 63;          // pixel within tile
        const int g = tid >> 6;          // which of the 2 tiles this round
        const int* yp = y + (size_t)b * HW + n0;
        for (int r = 0; r < TILES/2; ++r) {
            const int t  = 2*r + g;
            const int lb = yp[t*TPX + p];
            if (tid < 2*K_) cnt[tid] = 0;
            __syncthreads();
            atomicAdd(&cnt[g*K_ + lb], 1);
            __syncthreads();
            if (p == 0) {                // threads 0 and 64 scan their tile
                int run = 0;
                #pragma unroll
                for (int k = 0; k < K_; ++k) {
                    int c = cnt[g*K_ + k];
                    offs[t*(K_+1) + k] = run;
                    cnt[g*K_ + k] = run;     // reuse as scatter cursor
                    run += c;
                }
                offs[t*(K_+1) + K_] = run;   // == TPX
            }
            __syncthreads();
            int pos = atomicAdd(&cnt[g*K_ + lb], 1);
            lists[t*TPX + pos] = (unsigned short)p;
            __syncthreads();
        }
    }

    // class counts fall out of the sort offsets (one channel-group contributes)
    if (blockIdx.y == 0 && tid < K_) {
        int tot = 0;
        #pragma unroll
        for (int t = 0; t < TILES; ++t)
            tot += offs[t*(K_+1) + tid + 1] - offs[t*(K_+1) + tid];
        atomicAdd(&d_cnt[b*K_ + tid], tot);
    }

    // ---- main phase: stage (LDG.128) + accumulate (register acc) ----
    float sA[K_], qA[K_];
    #pragma unroll
    for (int k = 0; k < K_; ++k) { sA[k] = 0.f; qA[k] = 0.f; }

    const int px4 = tid & 15;            // float4 index along pixels (0..15)
    const int r0  = tid >> 4;            // base channel row (0..7)
    const float* xbase = x + ((size_t)(b*C_ + c0)) * HW + n0;
    const float* rowp  = tile + tid * ROWLEN;   // compute: thread = channel

    for (int t = 0; t < TILES; ++t) {
        // stage: 128ch x 64px tile; each thread: 16 independent LDG.128
        const float* xt = xbase + t*TPX + px4*4;
        #pragma unroll
        for (int i = 0; i < 16; ++i) {
            const int ch = r0 + i*8;
            float4 v = *(const float4*)(xt + (size_t)ch * HW);
            float* dst = tile + ch*ROWLEN + px4*4;
            dst[0] = v.x; dst[1] = v.y; dst[2] = v.z; dst[3] = v.w;
        }
        __syncthreads();

        // compute: label uniform per sorted position; per-run register acc
        const unsigned short* lst = lists + t*TPX;
        const int*            of  = offs  + t*(K_+1);
        #pragma unroll
        for (int k = 0; k < K_; ++k) {
            int j = of[k];
            const int e = of[k+1];
            float s0 = 0.f, q0 = 0.f, s1 = 0.f, q1 = 0.f;
            for (; j + 1 < e; j += 2) {
                float v0 = rowp[lst[j]];
                float v1 = rowp[lst[j+1]];
                s0 += v0; q0 = fmaf(v0, v0, q0);
                s1 += v1; q1 = fmaf(v1, v1, q1);
            }
            if (j < e) {
                float v0 = rowp[lst[j]];
                s0 += v0; q0 = fmaf(v0, v0, q0);
            }
            sA[k] += s0 + s1;
            qA[k] += q0 + q1;
        }
        __syncthreads();
    }

    // ---- flush: coalesced global atomics, one pair per (class, channel) ----
    const int base = (b*K_)*C_ + c0 + tid;
    #pragma unroll
    for (int k = 0; k < K_; ++k) {
        atomicAdd(&d_scrS[base + k*C_], sA[k]);
        atomicAdd(&d_scrQ[base + k*C_], qA[k]);
    }
}

// Finalize: means [B,K,C] | stds [B,K,C] | valid [B,K]  (all float32)
__global__ void finalize_kernel(float* __restrict__ out) {
    const int bk = blockIdx.x;      // 0..B*K-1
    const int c  = threadIdx.x;     // 0..C-1
    const int cc = d_cnt[bk];
    const float n     = (float)cc;
    const bool  valid = cc > COUNT_THRESH;
    const float s = d_scrS[bk*C_ + c];
    const float q = d_scrQ[bk*C_ + c];
    const float mean = s / fmaxf(n, 1.f);
    float var = (q - n*mean*mean) / fmaxf(n - 1.f, 1.f);
    var = fmaxf(var, 0.f);
    const float sd = sqrtf(valid ? var : 1.f) + EPS_;
    out[bk*C_ + c]            = valid ? mean : 0.f;
    out[B_*K_*C_ + bk*C_ + c] = valid ? sd   : 0.f;
    if (c == 0)
        out[2*B_*K_*C_ + bk] = valid ? 1.f : 0.f;
}

extern "C" void kernel_launch(void* const* d_in, const int* in_sizes, int n_in,
                              void* d_out, int out_size) {
    const float* x = (const float*)d_in[0];   // [B, C, H, W] f32
    const int*   y = (const int*)d_in[1];     // [B, H, W] int32
    float* out = (float*)d_out;

    zero_kernel<<<(B_*K_*C_ + 255)/256, 256>>>();

    dim3 grid(SEGS, C_/CBLK, B_);   // 128 x 2 x 4 = 1024 blocks
    moment_main_kernel<<<grid, CBLK, SMEM_BYTES>>>(x, y);

    finalize_kernel<<<B_*K_, C_>>>(out);
}